// round 14
// baseline (speedup 1.0000x reference)
#include <cuda_runtime.h>
#include <cuda_fp16.h>
#include <math.h>
#include <stdint.h>
#include <mma.h>

using namespace nvcuda;

// Problem constants
#define BB 4
#define NN 1024
#define CC 512
#define HH 8
#define DD 64
#define MR 4096            // B*N
#define TT 11              // conv taps (self + 10 neighbors)
#define KDIM 5632          // TT * CC

typedef unsigned long long ull;

// ---------------- device scratch ----------------
__device__ float  g_q[MR * CC];
__device__ float  g_k[MR * CC];
__device__ float  g_v[MR * CC];
__device__ __half g_Qh[MR * CC];          // half Q (GEMM A operand)
__device__ __half g_vh[MR * CC];          // half v (conv A operand)
__device__ __half g_convh[MR * CC];       // conv output (A of W2 GEMM)
__device__ __half g_xnh[MR * CC];         // LN output (A of Wo GEMM)
__device__ __half g_WT[KDIM * CC];        // conv weight, [o][t*512+c] half
__device__ __half g_WqT[CC * CC];
__device__ __half g_WkT[CC * CC];
__device__ __half g_WvT[CC * CC];
__device__ __half g_W2T[CC * CC];
__device__ __half g_WoT[CC * CC];
__device__ float  g_xloc[MR * CC];
__device__ float  g_x[MR * CC];
__device__ float  g_km[BB * CC];
__device__ float  g_kmp[BB * 8 * CC];
__device__ float  g_kv[BB * HH * DD * DD];
__device__ float  g_kvp[8 * BB * HH * DD * DD];
__device__ float  g_pvec[32 * 32 * 64];
__device__ float  g_pdiag[32 * 32];
__device__ float  g_invs[CC];
__device__ double g_lossbh[96];

// ---------------- cp.async helpers ----------------
__device__ __forceinline__ unsigned smem_u32(const void* p) {
    unsigned a;
    asm("{ .reg .u64 t; cvta.to.shared.u64 t, %1; cvt.u32.u64 %0, t; }" : "=r"(a) : "l"(p));
    return a;
}
__device__ __forceinline__ void cp16(unsigned dst, const void* src) {
    asm volatile("cp.async.ca.shared.global [%0], [%1], 16;" :: "r"(dst), "l"(src));
}
__device__ __forceinline__ void cp_commit() {
    asm volatile("cp.async.commit_group;" ::: "memory");
}
template <int N>
__device__ __forceinline__ void cp_wait() {
    asm volatile("cp.async.wait_group %0;" :: "n"(N) : "memory");
}

// ---------------- fp16 wmma GEMM core, cp.async double-buffered, 128x128 tile ----------------
// Templated on BK (64 or 128). D[128x128] per CTA. 256 threads = 8 warps, 4(m) x 2(n),
// warp tile 32x64. A: half MxK row-major; adj != null => conv gather (tap = k>>9).
// BT: [n][k] half. Output: float C (bias added) and/or half Ch. K % BK == 0.
// 2-stage double buffer, dynamic smem.
#define BKP 20                        // epilogue float staging stride

template <int BK>
__device__ __forceinline__ void gemm_core(
    const __half* __restrict__ A, const __half* __restrict__ BT,
    const float* __restrict__ bias, float* __restrict__ C, __half* __restrict__ Ch,
    int Kfull, const int* __restrict__ adj)
{
    constexpr int BKHs  = BK + 8;           // padded k-stride (halves)
    constexpr int TILEH = 128 * BKHs;       // halves per operand per stage
    constexpr int CPR   = BK / 8;           // 16B chunks per row
    constexpr int LPT   = CPR / 2;          // chunks per thread (256 threads, 128 rows)
    constexpr int KST   = BK / 16;          // wmma k-steps per stage

    extern __shared__ __half sm[];
    __half* Asm = sm;
    __half* Bsm = sm + 2 * TILEH;
    const unsigned sb = smem_u32(sm);
    const unsigned sbB = sb + 2 * TILEH * 2;

    const int tid = threadIdx.x;          // 256
    const int wid = tid >> 5, lane = tid & 31;
    const int bm = blockIdx.y * 128, bn = blockIdx.x * 128;
    const int wm = (wid & 3) * 32;        // warp m-offset
    const int wn = (wid >> 2) * 64;       // warp n-offset
    const int bat = bm >> 10;

    wmma::fragment<wmma::accumulator, 16, 16, 16, float> acc[2][4];
#pragma unroll
    for (int i = 0; i < 2; i++)
#pragma unroll
        for (int j = 0; j < 4; j++)
            wmma::fill_fragment(acc[i][j], 0.0f);

    const int T = Kfull / BK;

#define LOAD_STAGE(IT, S)                                                     \
    {                                                                         \
        const int k0 = (IT) * BK;                                             \
        int tap = 0, kin = k0;                                                \
        if (adj) { tap = k0 >> 9; kin = k0 & 511; }                           \
        const unsigned ab = sb + (S) * (TILEH * 2);                           \
        const unsigned bb = sbB + (S) * (TILEH * 2);                          \
        _Pragma("unroll")                                                     \
        for (int i = 0; i < LPT; i++) {                                       \
            int f = tid + i * 256;                                            \
            int row = f / CPR, c8 = (f % CPR) * 8;                            \
            const __half* srcA;                                               \
            if (adj) {                                                        \
                int gm = bm + row;                                            \
                int srow = tap ? ((bat << 10) + adj[gm * 10 + tap - 1]) : gm; \
                srcA = A + (size_t)srow * 512 + kin + c8;                     \
            } else {                                                          \
                srcA = A + (size_t)(bm + row) * Kfull + k0 + c8;              \
            }                                                                 \
            cp16(ab + (row * BKHs + c8) * 2, srcA);                           \
        }                                                                     \
        _Pragma("unroll")                                                     \
        for (int i = 0; i < LPT; i++) {                                       \
            int f = tid + i * 256;                                            \
            int row = f / CPR, c8 = (f % CPR) * 8;                            \
            cp16(bb + (row * BKHs + c8) * 2,                                  \
                 BT + (size_t)(bn + row) * Kfull + k0 + c8);                  \
        }                                                                     \
    }

    // prologue: stage 0
    LOAD_STAGE(0, 0);
    cp_commit();

    for (int it = 0; it < T; ++it) {
        cp_wait<0>();                     // stage `it` complete
        __syncthreads();                  // all warps done reading retiring buffer
        int ls = it + 1;
        if (ls < T) LOAD_STAGE(ls, ls & 1);
        cp_commit();
        const __half* As_ = Asm + (it & 1) * TILEH;
        const __half* Bs_ = Bsm + (it & 1) * TILEH;
#pragma unroll
        for (int kk = 0; kk < KST; kk++) {
            wmma::fragment<wmma::matrix_a, 16, 16, 16, __half, wmma::row_major> afr[2];
            wmma::fragment<wmma::matrix_b, 16, 16, 16, __half, wmma::col_major> bfr[4];
#pragma unroll
            for (int i = 0; i < 2; i++)
                wmma::load_matrix_sync(afr[i], As_ + (wm + i * 16) * BKHs + kk * 16, BKHs);
#pragma unroll
            for (int j = 0; j < 4; j++)
                wmma::load_matrix_sync(bfr[j], Bs_ + (wn + j * 16) * BKHs + kk * 16, BKHs);
#pragma unroll
            for (int i = 0; i < 2; i++)
#pragma unroll
                for (int j = 0; j < 4; j++)
                    wmma::mma_sync(acc[i][j], afr[i], bfr[j], acc[i][j]);
        }
    }

    cp_wait<0>();
    __syncthreads();                      // smem free for epilogue staging

    // epilogue: stage each 16x16 accum through per-warp float smem, add bias, write
    float* stage = reinterpret_cast<float*>(sm) + wid * (16 * BKP);
#pragma unroll
    for (int i = 0; i < 2; i++) {
#pragma unroll
        for (int j = 0; j < 4; j++) {
            wmma::store_matrix_sync(stage, acc[i][j], BKP, wmma::mem_row_major);
            __syncwarp();
#pragma unroll
            for (int t = 0; t < 8; t++) {
                int idx = lane * 8 + t;
                int r = idx >> 4, col = idx & 15;
                int gr = bm + wm + i * 16 + r;
                int gc = bn + wn + j * 16 + col;
                float val = stage[r * BKP + col] + bias[gc];
                if (C)  C[(size_t)gr * 512 + gc] = val;
                if (Ch) Ch[(size_t)gr * 512 + gc] = __float2half_rn(val);
            }
            __syncwarp();
        }
    }
#undef LOAD_STAGE
}

#define SMEM64  (2 * (128 * 72)  * 2 * 2)   // 73728 B  (BK=64,  2 stages, 2 ops)
#define SMEM128 (2 * (128 * 136) * 2 * 2)   // 139264 B (BK=128, 2 stages, 2 ops)

__global__ __launch_bounds__(256, 2) void gemm_qkv(
    const __half* __restrict__ Qh,
    const __half* __restrict__ WqT, const __half* __restrict__ WkT, const __half* __restrict__ WvT,
    const float* __restrict__ bq, const float* __restrict__ bk, const float* __restrict__ bv,
    float* __restrict__ q, float* __restrict__ k, float* __restrict__ v,
    __half* __restrict__ vh)
{
    int z = blockIdx.z;
    const __half* W = (z == 0) ? WqT : ((z == 1) ? WkT : WvT);
    const float* b = (z == 0) ? bq : ((z == 1) ? bk : bv);
    float* o = (z == 0) ? q : ((z == 1) ? k : v);
    gemm_core<64>(Qh, W, b, o, (z == 2) ? vh : nullptr, 512, nullptr);
}

__global__ __launch_bounds__(256, 2) void gemm_plain(
    const __half* __restrict__ A, const __half* __restrict__ BT,
    const float* __restrict__ bias, float* __restrict__ C)
{
    gemm_core<64>(A, BT, bias, C, nullptr, 512, nullptr);
}

// conv GEMM: BK=128 (44 stages), 1 CTA/SM; A = half v with adjacency gather
__global__ __launch_bounds__(256, 1) void gemm_conv(
    const __half* __restrict__ vh, const __half* __restrict__ WT,
    const float* __restrict__ bias, __half* __restrict__ Ch, const int* __restrict__ adj)
{
    gemm_core<128>(vh, WT, bias, nullptr, Ch, 5632, adj);
}

// ---------------- float -> half convert (A-operand prep) ----------------
__global__ void to_half(const float* __restrict__ src, __half* __restrict__ dst) {
    int i = (blockIdx.x * 256 + threadIdx.x) * 8;   // grid covers MR*CC
    float4 a = *(const float4*)(src + i);
    float4 b = *(const float4*)(src + i + 4);
    __half2 h[4];
    h[0] = __floats2half2_rn(a.x, a.y);
    h[1] = __floats2half2_rn(a.z, a.w);
    h[2] = __floats2half2_rn(b.x, b.y);
    h[3] = __floats2half2_rn(b.z, b.w);
    *(uint4*)(dst + i) = *(uint4*)h;
}

// ---------------- weight transposes (to [n][k], half) ----------------
__global__ void transpose512(
    const float* __restrict__ Wq, const float* __restrict__ Wk, const float* __restrict__ Wv,
    const float* __restrict__ W2, const float* __restrict__ Wo,
    __half* __restrict__ WqT, __half* __restrict__ WkT, __half* __restrict__ WvT,
    __half* __restrict__ W2T, __half* __restrict__ WoT)
{
    int z = blockIdx.z;
    const float* src = (z == 0) ? Wq : (z == 1) ? Wk : (z == 2) ? Wv : (z == 3) ? W2 : Wo;
    __half* dst = (z == 0) ? WqT : (z == 1) ? WkT : (z == 2) ? WvT : (z == 3) ? W2T : WoT;
    __shared__ float s[32][33];
    int tx = threadIdx.x, ty = threadIdx.y;
    int x = blockIdx.x * 32 + tx;
#pragma unroll
    for (int j = 0; j < 4; j++) {
        int y = blockIdx.y * 32 + ty + j * 8;
        s[ty + j * 8][tx] = src[y * 512 + x];
    }
    __syncthreads();
#pragma unroll
    for (int j = 0; j < 4; j++) {
        int yo = blockIdx.x * 32 + ty + j * 8;   // n index
        dst[yo * 512 + blockIdx.y * 32 + tx] = __float2half_rn(s[tx][ty + j * 8]);
    }
}

// Wconv permute, output-coalesced: WT[o][t*512+c] = Wconv[o][c*11+t], half.
__global__ void transpose_wconv(const float* __restrict__ W, __half* __restrict__ WT) {
    int o = blockIdx.x;                       // 512 rows
    const float* src = W + (size_t)o * KDIM;
    __half* dst = WT + (size_t)o * KDIM;
    for (int j = threadIdx.x; j < KDIM; j += 512) {
        int t = j >> 9, c = j & 511;          // output index j = t*512 + c
        dst[j] = __float2half_rn(src[c * 11 + t]);
    }
}

// ---------------- 1/softplus(scale) precompute ----------------
__device__ __forceinline__ float softplusf(float x) {
    return (x > 20.f) ? x : log1pf(expf(x));
}
__global__ void invs_kernel(const float* __restrict__ scp, float* __restrict__ invs) {
    int c = blockIdx.x * 256 + threadIdx.x;
    if (c < CC) invs[c] = 1.f / softplusf(scp[c]);
}

// ---------------- q/k transform: relu+eps, *invscale, focus (cube) ----------------
__global__ void qk_focus(float* __restrict__ q, float* __restrict__ k,
                         const float* __restrict__ invs) {
    int row = blockIdx.x;
    int tid = threadIdx.x;            // 256 = 8 warps
    int warp = tid >> 5, lane = tid & 31;
    __shared__ float ws[8];
    float* p = (blockIdx.y ? k : q) + (size_t)row * CC;
    int c0 = tid, c1 = tid + 256;
    float v0 = (fmaxf(p[c0], 0.f) + 1e-6f) * invs[c0];
    float v1 = (fmaxf(p[c1], 0.f) + 1e-6f) * invs[c1];
    float s = v0 * v0 + v1 * v1;
#pragma unroll
    for (int o = 16; o; o >>= 1) s += __shfl_xor_sync(0xffffffffu, s, o);
    if (lane == 0) ws[warp] = s;
    __syncthreads();
    float tot = 0.f;
#pragma unroll
    for (int j = 0; j < 8; j++) tot += ws[j];
    float nrm = sqrtf(tot);
    float inv = 1.f / (nrm + 1e-6f);
    float u0 = v0 * inv, u1 = v1 * inv;
    p[c0] = u0 * u0 * u0 * nrm;
    p[c1] = u1 * u1 * u1 * nrm;
}

// ---------------- kmean partials + reduce ----------------
__global__ void kmean_part(const float* __restrict__ k, float* __restrict__ kmp) {
    int b = blockIdx.y, ch = blockIdx.x;   // grid (8, BB), 512 threads
    int c = threadIdx.x;
    const float* p = k + (size_t)(b * NN + ch * 128) * CC + c;
    float s = 0.f;
    for (int n = 0; n < 128; n++) s += p[n * CC];
    kmp[(b * 8 + ch) * CC + c] = s;
}
__global__ void kmean_red(const float* __restrict__ kmp, float* __restrict__ km) {
    int i = blockIdx.x * 256 + threadIdx.x;  // BB*CC = 2048
    int b = i >> 9, c = i & 511;
    float s = 0.f;
#pragma unroll
    for (int j = 0; j < 8; j++) s += kmp[(b * 8 + j) * CC + c];
    km[i] = s * (1.f / NN);
}

// ---------------- kv partials: 8 N-splits of 128 rows each ----------------
__global__ __launch_bounds__(256) void kv_part(
    const float* __restrict__ k, const float* __restrict__ v, float* __restrict__ kvp)
{
    int bh = blockIdx.x, b = bh >> 3, h = bh & 7;
    int sp = blockIdx.y;
    __shared__ float sk[8][64], sv[8][64];
    int t = threadIdx.x;
    int dI = (t >> 4) << 2, eI = (t & 15) << 2;
    const float* kb = k + b * NN * CC + h * 64;
    const float* vb = v + b * NN * CC + h * 64;
    float acc[4][4] = {};
    int n0s = sp * 128, n0e = n0s + 128;
    for (int n0 = n0s; n0 < n0e; n0 += 8) {
#pragma unroll
        for (int j = 0; j < 2; j++) {
            int idx = t + j * 256;
            int rr = idx >> 6, cc = idx & 63;
            sk[rr][cc] = kb[(n0 + rr) * CC + cc];
            sv[rr][cc] = vb[(n0 + rr) * CC + cc];
        }
        __syncthreads();
#pragma unroll
        for (int r = 0; r < 8; r++) {
            float a[4], bv4[4];
#pragma unroll
            for (int i = 0; i < 4; i++) a[i] = sk[r][dI + i];
#pragma unroll
            for (int j = 0; j < 4; j++) bv4[j] = sv[r][eI + j];
#pragma unroll
            for (int i = 0; i < 4; i++)
#pragma unroll
                for (int j = 0; j < 4; j++)
                    acc[i][j] += a[i] * bv4[j];
        }
        __syncthreads();
    }
    float* dst = kvp + (sp * 32 + bh) * 4096;
#pragma unroll
    for (int i = 0; i < 4; i++)
#pragma unroll
        for (int j = 0; j < 4; j++)
            dst[(dI + i) * 64 + eI + j] = acc[i][j];
}

__global__ void kv_reduce(const float* __restrict__ kvp, float* __restrict__ kv) {
    int idx = blockIdx.x * 256 + threadIdx.x;   // 131072
    float s = 0.f;
#pragma unroll
    for (int sp = 0; sp < 8; sp++) s += kvp[sp * 131072 + idx];
    kv[idx] = s * (1.f / NN);
}

// ---------------- attention output + x_local add + fused LayerNorm ----------------
__global__ __launch_bounds__(512) void attn_ln_kernel(
    const float* __restrict__ q, const float* __restrict__ km,
    const float* __restrict__ kv, const float* __restrict__ xloc,
    const float* __restrict__ lng, const float* __restrict__ lnb,
    float* __restrict__ x, __half* __restrict__ xnh)
{
    int row = blockIdx.x;
    int b = row >> 10;
    int c = threadIdx.x;              // 512 = 16 warps
    int warp = c >> 5, lane = c & 31;
    __shared__ float qs[512];
    __shared__ float zp[16];          // per-warp q*km partial sums
    __shared__ float rs[16], rq[16];  // LN partials
    float qv = q[(size_t)row * CC + c];
    qs[c] = qv;
    float prod = qv * km[b * CC + c];
#pragma unroll
    for (int o = 16; o; o >>= 1) prod += __shfl_xor_sync(0xffffffffu, prod, o);
    if (lane == 0) zp[warp] = prod;
    __syncthreads();                  // qs full + zp ready
    int h = c >> 6, e = c & 63;
    float z = 1.f / (zp[h * 2] + zp[h * 2 + 1] + 1e-6f);
    const float* kvp = kv + ((b * 8 + h) * 64) * 64 + e;
    float acc = 0.f;
#pragma unroll 8
    for (int d = 0; d < 64; d++) acc += qs[h * 64 + d] * kvp[d * 64];
    float xv = acc * z + xloc[(size_t)row * CC + c];
    x[(size_t)row * CC + c] = xv;
    float s = xv, sq = xv * xv;
#pragma unroll
    for (int o = 16; o; o >>= 1) {
        s  += __shfl_xor_sync(0xffffffffu, s, o);
        sq += __shfl_xor_sync(0xffffffffu, sq, o);
    }
    if (lane == 0) { rs[warp] = s; rq[warp] = sq; }
    __syncthreads();
    float tot = 0.f, totq = 0.f;
#pragma unroll
    for (int j = 0; j < 16; j++) { tot += rs[j]; totq += rq[j]; }
    float mu = tot * (1.f / CC);
    float var = totq * (1.f / CC) - mu * mu;
    float inv = rsqrtf(var + 1e-5f);
    xnh[(size_t)row * CC + c] = __float2half_rn((xv - mu) * inv * lng[c] + lnb[c]);
}

// ---------------- disagreement phase 1 ----------------
__global__ void disagree_part(const float* __restrict__ x, int rowsPerBlk, int rowStride,
                              int strideB, int strideH,
                              float* __restrict__ pvec, float* __restrict__ pdiag)
{
    int bh = blockIdx.x, b = bh >> 3, h = bh & 7;
    int s = blockIdx.y, S = gridDim.y;
    const float* p = x + b * strideB + h * strideH + s * rowsPerBlk * rowStride;
    int l = threadIdx.x; // 32
    float s0 = 0.f, s1 = 0.f, diag = 0.f;
    for (int n = 0; n < rowsPerBlk; n++) {
        const float* r = p + n * rowStride;
        float v0 = r[l], v1 = r[l + 32];
        float sq = v0 * v0 + v1 * v1;
#pragma unroll
        for (int o = 16; o; o >>= 1) sq += __shfl_xor_sync(0xffffffffu, sq, o);
        float inv = 1.f / fmaxf(sqrtf(sq), 1e-12f);
        float h0 = v0 * inv, h1 = v1 * inv;
        s0 += h0; s1 += h1;
        diag += h0 * h0 + h1 * h1;
    }
    float* pv = pvec + (bh * S + s) * 64;
    pv[l] = s0; pv[l + 32] = s1;
#pragma unroll
    for (int o = 16; o; o >>= 1) diag += __shfl_xor_sync(0xffffffffu, diag, o);
    if (l == 0) pdiag[bh * S + s] = diag;
}

__global__ void disagree_reduce(const float* __restrict__ pvec, const float* __restrict__ pdiag,
                                int S, double* __restrict__ Lb)
{
    int bh = blockIdx.x;
    int l = threadIdx.x; // 64
    double v = 0.0;
    for (int s = 0; s < S; s++) v += (double)pvec[(bh * S + s) * 64 + l];
    __shared__ double sh[64];
    sh[l] = v * v;
    __syncthreads();
    for (int o = 32; o; o >>= 1) {
        if (l < o) sh[l] += sh[l + o];
        __syncthreads();
    }
    if (l == 0) {
        double d = 0.0;
        for (int s = 0; s < S; s++) d += (double)pdiag[bh * S + s];
        Lb[bh] = sh[0] - d;
    }
}

__global__ void disagree_small(const float* __restrict__ x, int nRows, int rowStride,
                               int strideB, int strideH, double* __restrict__ Lb)
{
    int bh = blockIdx.x, b = bh >> 3, h = bh & 7;
    const float* p = x + b * strideB + h * strideH;
    int l = threadIdx.x; // 32
    double s0 = 0.0, s1 = 0.0, diag = 0.0;
    for (int n = 0; n < nRows; n++) {
        const float* r = p + n * rowStride;
        float v0 = r[l], v1 = r[l + 32];
        float sq = v0 * v0 + v1 * v1;
#pragma unroll
        for (int o = 16; o; o >>= 1) sq += __shfl_xor_sync(0xffffffffu, sq, o);
        float inv = 1.f / fmaxf(sqrtf(sq), 1e-12f);
        float h0 = v0 * inv, h1 = v1 * inv;
        s0 += (double)h0; s1 += (double)h1;
        diag += (double)(h0 * h0 + h1 * h1);
    }
    double val = s0 * s0 + s1 * s1;
#pragma unroll
    for (int o = 16; o; o >>= 1) {
        val += __shfl_xor_sync(0xffffffffu, val, o);
        diag += __shfl_xor_sync(0xffffffffu, diag, o);
    }
    if (l == 0) Lb[bh] = val - diag;
}

// ---------------- final loss combine ----------------
__global__ void finish_loss(const double* __restrict__ Lb, float* dst, int doWrite) {
    if (doWrite && threadIdx.x == 0 && blockIdx.x == 0) {
        double l0 = 0.0, l1 = 0.0, l2 = 0.0;
        for (int i = 0; i < 32; i++) { l0 += Lb[i]; l1 += Lb[32 + i]; l2 += Lb[64 + i]; }
        double dbig = 4.0 * 8.0 * 1024.0 * 1024.0;
        double dsml = 4.0 * 8.0 * 64.0 * 64.0;
        dst[0] = (float)((l0 / dbig + l1 / dsml + l2 / dbig) / 3.0);
    }
}

// ---------------- launch ----------------
extern "C" void kernel_launch(void* const* d_in, const int* in_sizes, int n_in,
                              void* d_out, int out_size)
{
    const float* Q      = (const float*)d_in[0];
    const int*   adj    = (const int*)  d_in[1];
    const float* Wq     = (const float*)d_in[2];
    const float* bq     = (const float*)d_in[3];
    const float* Wk     = (const float*)d_in[4];
    const float* bk     = (const float*)d_in[5];
    const float* Wv     = (const float*)d_in[6];
    const float* bv     = (const float*)d_in[7];
    const float* scp    = (const float*)d_in[8];
    const float* Wconv  = (const float*)d_in[9];
    const float* bconv  = (const float*)d_in[10];
    const float* W2     = (const float*)d_in[11];
    const float* b2     = (const float*)d_in[12];
    const float* ln_g   = (const float*)d_in[13];
    const float* ln_b   = (const float*)d_in[14];
    const float* Wo     = (const float*)d_in[15];
    const float* bo     = (const float*)d_in[16];
    float* out = (float*)d_out;

    float *q, *k, *v, *xloc, *x, *km, *kmp, *kv, *kvp, *pvec, *pdiag, *invs;
    __half *Qh, *vh, *convh, *xnh, *WT, *WqT, *WkT, *WvT, *W2T, *WoT;
    double* Lb;
    cudaGetSymbolAddress((void**)&q,     g_q);
    cudaGetSymbolAddress((void**)&k,     g_k);
    cudaGetSymbolAddress((void**)&v,     g_v);
    cudaGetSymbolAddress((void**)&Qh,    g_Qh);
    cudaGetSymbolAddress((void**)&vh,    g_vh);
    cudaGetSymbolAddress((void**)&convh, g_convh);
    cudaGetSymbolAddress((void**)&xnh,   g_xnh);
    cudaGetSymbolAddress((void**)&WT,    g_WT);
    cudaGetSymbolAddress((void**)&WqT,   g_WqT);
    cudaGetSymbolAddress((void**)&WkT,   g_WkT);
    cudaGetSymbolAddress((void**)&WvT,   g_WvT);
    cudaGetSymbolAddress((void**)&W2T,   g_W2T);
    cudaGetSymbolAddress((void**)&WoT,   g_WoT);
    cudaGetSymbolAddress((void**)&xloc,  g_xloc);
    cudaGetSymbolAddress((void**)&x,     g_x);
    cudaGetSymbolAddress((void**)&km,    g_km);
    cudaGetSymbolAddress((void**)&kmp,   g_kmp);
    cudaGetSymbolAddress((void**)&kv,    g_kv);
    cudaGetSymbolAddress((void**)&kvp,   g_kvp);
    cudaGetSymbolAddress((void**)&pvec,  g_pvec);
    cudaGetSymbolAddress((void**)&pdiag, g_pdiag);
    cudaGetSymbolAddress((void**)&invs,  g_invs);
    cudaGetSymbolAddress((void**)&Lb,    g_lossbh);

    // dynamic-smem opt-in (host attribute set; not a stream op, graph-capture safe)
    cudaFuncSetAttribute(gemm_qkv,   cudaFuncAttributeMaxDynamicSharedMemorySize, SMEM64);
    cudaFuncSetAttribute(gemm_plain, cudaFuncAttributeMaxDynamicSharedMemorySize, SMEM64);
    cudaFuncSetAttribute(gemm_conv,  cudaFuncAttributeMaxDynamicSharedMemorySize, SMEM128);

    dim3 gG(4, 32);           // 128x128 tiles over 4096x512 => 128 CTAs
    dim3 gG3(4, 32, 3);       // qkv => 384 CTAs
    const int CVT_GRID = MR * CC / 2048;   // to_half grid (8 floats/thread)

    invs_kernel<<<2, 256>>>(scp, invs);

    // weight prep (half, [n][k] layout)
    transpose512<<<dim3(16, 16, 5), dim3(32, 8)>>>(Wq, Wk, Wv, W2, Wo, WqT, WkT, WvT, W2T, WoT);
    transpose_wconv<<<512, 512>>>(Wconv, WT);

    // A-operand prep + projections (fused q/k/v over grid.z; v also emitted as half)
    to_half<<<CVT_GRID, 256>>>(Q, Qh);
    gemm_qkv<<<gG3, 256, SMEM64>>>(Qh, WqT, WkT, WvT, bq, bk, bv, q, k, v, vh);

    // loss_local on head-view of v
    disagree_part<<<dim3(32, 32), 32>>>(v, NN / 32, CC, NN * CC, DD, pvec, pdiag);
    disagree_reduce<<<32, 64>>>(pvec, pdiag, 32, Lb + 0);

    // local branch: half conv GEMM (fused gather, BK=128) then W2 GEMM
    gemm_conv<<<gG, 256, SMEM128>>>(vh, WT, bconv, convh, adj);
    gemm_plain<<<gG, 256, SMEM64>>>(convh, W2T, b2, xloc);

    // q/k elementwise transform (one launch)
    qk_focus<<<dim3(MR, 2), 256>>>(q, k, invs);

    // kmean, kv
    kmean_part<<<dim3(8, BB), 512>>>(k, kmp);
    kmean_red<<<8, 256>>>(kmp, km);
    kv_part<<<dim3(32, 8), 256>>>(k, v, kvp);
    kv_reduce<<<512, 256>>>(kvp, kv);

    // loss_kv
    disagree_small<<<32, 32>>>(kv, DD, DD, HH * DD * DD, DD * DD, Lb + 32);

    // attention out + local add + fused LayerNorm (xn written as half)
    attn_ln_kernel<<<MR, 512>>>(q, km, kv, xloc, ln_g, ln_b, x, xnh);

    // loss_out on flat reshape view
    disagree_part<<<dim3(32, 32), 32>>>(x, NN / 32, DD, NN * CC, NN * CC / HH, pvec, pdiag);
    disagree_reduce<<<32, 64>>>(pvec, pdiag, 32, Lb + 64);

    // output projection
    gemm_plain<<<gG, 256, SMEM64>>>(xnh, WoT, bo, out);

    // loss scalar appended after the (B,N,C) output, if the buffer has room
    finish_loss<<<1, 32>>>(Lb, out + MR * CC, (out_size > MR * CC) ? 1 : 0);
}

// round 15
// speedup vs baseline: 1.5960x; 1.5960x over previous
#include <cuda_runtime.h>
#include <cuda_fp16.h>
#include <math.h>
#include <stdint.h>
#include <mma.h>

using namespace nvcuda;

// Problem constants
#define BB 4
#define NN 1024
#define CC 512
#define HH 8
#define DD 64
#define MR 4096            // B*N
#define TT 11              // conv taps (self + 10 neighbors)
#define KDIM 5632          // TT * CC

typedef unsigned long long ull;

// ---------------- device scratch ----------------
__device__ float  g_q[MR * CC];
__device__ float  g_k[MR * CC];
__device__ float  g_v[MR * CC];
__device__ __half g_Qh[MR * CC];          // half Q (GEMM A operand)
__device__ __half g_vh[MR * CC];          // half v (conv A operand)
__device__ __half g_convh[MR * CC];       // conv output (A of W2 GEMM)
__device__ __half g_xnh[MR * CC];         // LN output (A of Wo GEMM)
__device__ __half g_WT[KDIM * CC];        // conv weight, [o][t*512+c] half
__device__ __half g_WqT[CC * CC];
__device__ __half g_WkT[CC * CC];
__device__ __half g_WvT[CC * CC];
__device__ __half g_W2T[CC * CC];
__device__ __half g_WoT[CC * CC];
__device__ float  g_part[2 * MR * CC];    // conv split-K partials (16 MB)
__device__ float  g_xloc[MR * CC];
__device__ float  g_x[MR * CC];
__device__ float  g_km[BB * CC];
__device__ float  g_kmp[BB * 8 * CC];
__device__ float  g_kv[BB * HH * DD * DD];
__device__ float  g_kvp[8 * BB * HH * DD * DD];
__device__ float  g_pvec[32 * 32 * 64];
__device__ float  g_pdiag[32 * 32];
__device__ float  g_invs[CC];
__device__ double g_lossbh[96];

// ---------------- cp.async helpers ----------------
__device__ __forceinline__ unsigned smem_u32(const void* p) {
    unsigned a;
    asm("{ .reg .u64 t; cvta.to.shared.u64 t, %1; cvt.u32.u64 %0, t; }" : "=r"(a) : "l"(p));
    return a;
}
__device__ __forceinline__ void cp16(unsigned dst, const void* src) {
    asm volatile("cp.async.ca.shared.global [%0], [%1], 16;" :: "r"(dst), "l"(src));
}
__device__ __forceinline__ void cp_commit() {
    asm volatile("cp.async.commit_group;" ::: "memory");
}
template <int N>
__device__ __forceinline__ void cp_wait() {
    asm volatile("cp.async.wait_group %0;" :: "n"(N) : "memory");
}

// ---------------- fp16 wmma GEMM core, cp.async double-buffered, 128x128 tile ----------------
// BK=64 (validated optimum: 2 CTAs/SM co-residency required). 256 threads = 8 warps,
// 4(m) x 2(n), warp tile 32x64. A: half MxK row-major; adj != null => conv gather.
// BT: [n][k] half. Output: float C (+bias) and/or half Ch. Processes nStages BK=64
// chunks from kStart. bias may be null (raw partial).
#define BKH 72                        // padded k-stride in halves (64 + 8)
#define TILE_H (128 * BKH)            // halves per operand per stage
#define SMEM_BYTES (2 * TILE_H * 2 * 2)   // 73728
#define BKP 20                        // epilogue float staging stride

__device__ __forceinline__ void gemm_core(
    const __half* __restrict__ A, const __half* __restrict__ BT,
    const float* __restrict__ bias, float* __restrict__ C, __half* __restrict__ Ch,
    int Kfull, int kStart, int nStages, const int* __restrict__ adj)
{
    extern __shared__ __half sm[];
    __half* Asm = sm;
    __half* Bsm = sm + 2 * TILE_H;
    const unsigned sb = smem_u32(sm);
    const unsigned sbB = sb + 2 * TILE_H * 2;

    const int tid = threadIdx.x;          // 256
    const int wid = tid >> 5, lane = tid & 31;
    const int bm = blockIdx.y * 128, bn = blockIdx.x * 128;
    const int wm = (wid & 3) * 32;        // warp m-offset
    const int wn = (wid >> 2) * 64;       // warp n-offset
    const int bat = bm >> 10;

    wmma::fragment<wmma::accumulator, 16, 16, 16, float> acc[2][4];
#pragma unroll
    for (int i = 0; i < 2; i++)
#pragma unroll
        for (int j = 0; j < 4; j++)
            wmma::fill_fragment(acc[i][j], 0.0f);

#define LOAD_STAGE(IT, S)                                                     \
    {                                                                         \
        const int k0 = kStart + ((IT) << 6);                                  \
        int tap = 0, kin = k0;                                                \
        if (adj) { tap = k0 >> 9; kin = k0 & 511; }                           \
        const unsigned ab = sb + (S) * (TILE_H * 2);                          \
        const unsigned bb = sbB + (S) * (TILE_H * 2);                         \
        _Pragma("unroll")                                                     \
        for (int i = 0; i < 4; i++) {                                         \
            int f = tid + i * 256;                                            \
            int row = f >> 3, c8 = (f & 7) * 8;                               \
            const __half* srcA;                                               \
            if (adj) {                                                        \
                int gm = bm + row;                                            \
                int srow = tap ? ((bat << 10) + adj[gm * 10 + tap - 1]) : gm; \
                srcA = A + (size_t)srow * 512 + kin + c8;                     \
            } else {                                                          \
                srcA = A + (size_t)(bm + row) * Kfull + k0 + c8;              \
            }                                                                 \
            cp16(ab + (row * BKH + c8) * 2, srcA);                            \
        }                                                                     \
        _Pragma("unroll")                                                     \
        for (int i = 0; i < 4; i++) {                                         \
            int f = tid + i * 256;                                            \
            int row = f >> 3, c8 = (f & 7) * 8;                               \
            cp16(bb + (row * BKH + c8) * 2,                                   \
                 BT + (size_t)(bn + row) * Kfull + k0 + c8);                  \
        }                                                                     \
    }

    // prologue: stage 0
    LOAD_STAGE(0, 0);
    cp_commit();

    for (int it = 0; it < nStages; ++it) {
        cp_wait<0>();                     // stage `it` complete
        __syncthreads();                  // all warps done reading retiring buffer
        int ls = it + 1;
        if (ls < nStages) LOAD_STAGE(ls, ls & 1);
        cp_commit();
        const __half* As_ = Asm + (it & 1) * TILE_H;
        const __half* Bs_ = Bsm + (it & 1) * TILE_H;
#pragma unroll
        for (int kk = 0; kk < 4; kk++) {
            wmma::fragment<wmma::matrix_a, 16, 16, 16, __half, wmma::row_major> afr[2];
            wmma::fragment<wmma::matrix_b, 16, 16, 16, __half, wmma::col_major> bfr[4];
#pragma unroll
            for (int i = 0; i < 2; i++)
                wmma::load_matrix_sync(afr[i], As_ + (wm + i * 16) * BKH + kk * 16, BKH);
#pragma unroll
            for (int j = 0; j < 4; j++)
                wmma::load_matrix_sync(bfr[j], Bs_ + (wn + j * 16) * BKH + kk * 16, BKH);
#pragma unroll
            for (int i = 0; i < 2; i++)
#pragma unroll
                for (int j = 0; j < 4; j++)
                    wmma::mma_sync(acc[i][j], afr[i], bfr[j], acc[i][j]);
        }
    }

    cp_wait<0>();
    __syncthreads();                      // smem free for epilogue staging

    // epilogue: stage each 16x16 accum through per-warp float smem, add bias, write
    float* stage = reinterpret_cast<float*>(sm) + wid * (16 * BKP);
#pragma unroll
    for (int i = 0; i < 2; i++) {
#pragma unroll
        for (int j = 0; j < 4; j++) {
            wmma::store_matrix_sync(stage, acc[i][j], BKP, wmma::mem_row_major);
            __syncwarp();
#pragma unroll
            for (int t = 0; t < 8; t++) {
                int idx = lane * 8 + t;
                int r = idx >> 4, col = idx & 15;
                int gr = bm + wm + i * 16 + r;
                int gc = bn + wn + j * 16 + col;
                float val = stage[r * BKP + col] + (bias ? bias[gc] : 0.0f);
                if (C)  C[(size_t)gr * 512 + gc] = val;
                if (Ch) Ch[(size_t)gr * 512 + gc] = __float2half_rn(val);
            }
            __syncwarp();
        }
    }
#undef LOAD_STAGE
}

__global__ __launch_bounds__(256, 2) void gemm_qkv(
    const __half* __restrict__ Qh,
    const __half* __restrict__ WqT, const __half* __restrict__ WkT, const __half* __restrict__ WvT,
    const float* __restrict__ bq, const float* __restrict__ bk, const float* __restrict__ bv,
    float* __restrict__ q, float* __restrict__ k, float* __restrict__ v,
    __half* __restrict__ vh)
{
    int z = blockIdx.z;
    const __half* W = (z == 0) ? WqT : ((z == 1) ? WkT : WvT);
    const float* b = (z == 0) ? bq : ((z == 1) ? bk : bv);
    float* o = (z == 0) ? q : ((z == 1) ? k : v);
    gemm_core(Qh, W, b, o, (z == 2) ? vh : nullptr, 512, 0, 8, nullptr);
}

__global__ __launch_bounds__(256, 2) void gemm_plain(
    const __half* __restrict__ A, const __half* __restrict__ BT,
    const float* __restrict__ bias, float* __restrict__ C)
{
    gemm_core(A, BT, bias, C, nullptr, 512, 0, 8, nullptr);
}

// conv GEMM split-K=2: z in {0,1}, 44 BK=64 stages each, raw fp32 partials
__global__ __launch_bounds__(256, 2) void gemm_conv_sk(
    const __half* __restrict__ vh, const __half* __restrict__ WT,
    float* __restrict__ part, const int* __restrict__ adj)
{
    int z = blockIdx.z;
    gemm_core(vh, WT, nullptr, part + (size_t)z * MR * 512, nullptr,
              5632, z * 2816, 44, adj);
}

// conv reduce: convh = half(p0 + p1 + bias)
__global__ void conv_reduce(const float* __restrict__ part, const float* __restrict__ bias,
                            __half* __restrict__ convh)
{
    int idx = blockIdx.x * 256 + threadIdx.x;   // MR*CC
    float s = part[idx] + part[MR * CC + idx] + bias[idx & 511];
    convh[idx] = __float2half_rn(s);
}

// ---------------- float -> half convert (A-operand prep) ----------------
__global__ void to_half(const float* __restrict__ src, __half* __restrict__ dst) {
    int i = (blockIdx.x * 256 + threadIdx.x) * 8;   // grid covers MR*CC
    float4 a = *(const float4*)(src + i);
    float4 b = *(const float4*)(src + i + 4);
    __half2 h[4];
    h[0] = __floats2half2_rn(a.x, a.y);
    h[1] = __floats2half2_rn(a.z, a.w);
    h[2] = __floats2half2_rn(b.x, b.y);
    h[3] = __floats2half2_rn(b.z, b.w);
    *(uint4*)(dst + i) = *(uint4*)h;
}

// ---------------- weight transposes (to [n][k], half) ----------------
__global__ void transpose512(
    const float* __restrict__ Wq, const float* __restrict__ Wk, const float* __restrict__ Wv,
    const float* __restrict__ W2, const float* __restrict__ Wo,
    __half* __restrict__ WqT, __half* __restrict__ WkT, __half* __restrict__ WvT,
    __half* __restrict__ W2T, __half* __restrict__ WoT)
{
    int z = blockIdx.z;
    const float* src = (z == 0) ? Wq : (z == 1) ? Wk : (z == 2) ? Wv : (z == 3) ? W2 : Wo;
    __half* dst = (z == 0) ? WqT : (z == 1) ? WkT : (z == 2) ? WvT : (z == 3) ? W2T : WoT;
    __shared__ float s[32][33];
    int tx = threadIdx.x, ty = threadIdx.y;
    int x = blockIdx.x * 32 + tx;
#pragma unroll
    for (int j = 0; j < 4; j++) {
        int y = blockIdx.y * 32 + ty + j * 8;
        s[ty + j * 8][tx] = src[y * 512 + x];
    }
    __syncthreads();
#pragma unroll
    for (int j = 0; j < 4; j++) {
        int yo = blockIdx.x * 32 + ty + j * 8;   // n index
        dst[yo * 512 + blockIdx.y * 32 + tx] = __float2half_rn(s[tx][ty + j * 8]);
    }
}

// Wconv permute, output-coalesced: WT[o][t*512+c] = Wconv[o][c*11+t], half.
__global__ void transpose_wconv(const float* __restrict__ W, __half* __restrict__ WT) {
    int o = blockIdx.x;                       // 512 rows
    const float* src = W + (size_t)o * KDIM;
    __half* dst = WT + (size_t)o * KDIM;
    for (int j = threadIdx.x; j < KDIM; j += 512) {
        int t = j >> 9, c = j & 511;          // output index j = t*512 + c
        dst[j] = __float2half_rn(src[c * 11 + t]);
    }
}

// ---------------- 1/softplus(scale) precompute ----------------
__device__ __forceinline__ float softplusf(float x) {
    return (x > 20.f) ? x : log1pf(expf(x));
}
__global__ void invs_kernel(const float* __restrict__ scp, float* __restrict__ invs) {
    int c = blockIdx.x * 256 + threadIdx.x;
    if (c < CC) invs[c] = 1.f / softplusf(scp[c]);
}

// ---------------- q/k transform: relu+eps, *invscale, focus (cube) ----------------
__global__ void qk_focus(float* __restrict__ q, float* __restrict__ k,
                         const float* __restrict__ invs) {
    int row = blockIdx.x;
    int tid = threadIdx.x;            // 256 = 8 warps
    int warp = tid >> 5, lane = tid & 31;
    __shared__ float ws[8];
    float* p = (blockIdx.y ? k : q) + (size_t)row * CC;
    int c0 = tid, c1 = tid + 256;
    float v0 = (fmaxf(p[c0], 0.f) + 1e-6f) * invs[c0];
    float v1 = (fmaxf(p[c1], 0.f) + 1e-6f) * invs[c1];
    float s = v0 * v0 + v1 * v1;
#pragma unroll
    for (int o = 16; o; o >>= 1) s += __shfl_xor_sync(0xffffffffu, s, o);
    if (lane == 0) ws[warp] = s;
    __syncthreads();
    float tot = 0.f;
#pragma unroll
    for (int j = 0; j < 8; j++) tot += ws[j];
    float nrm = sqrtf(tot);
    float inv = 1.f / (nrm + 1e-6f);
    float u0 = v0 * inv, u1 = v1 * inv;
    p[c0] = u0 * u0 * u0 * nrm;
    p[c1] = u1 * u1 * u1 * nrm;
}

// ---------------- kmean partials + reduce ----------------
__global__ void kmean_part(const float* __restrict__ k, float* __restrict__ kmp) {
    int b = blockIdx.y, ch = blockIdx.x;   // grid (8, BB), 512 threads
    int c = threadIdx.x;
    const float* p = k + (size_t)(b * NN + ch * 128) * CC + c;
    float s = 0.f;
    for (int n = 0; n < 128; n++) s += p[n * CC];
    kmp[(b * 8 + ch) * CC + c] = s;
}
__global__ void kmean_red(const float* __restrict__ kmp, float* __restrict__ km) {
    int i = blockIdx.x * 256 + threadIdx.x;  // BB*CC = 2048
    int b = i >> 9, c = i & 511;
    float s = 0.f;
#pragma unroll
    for (int j = 0; j < 8; j++) s += kmp[(b * 8 + j) * CC + c];
    km[i] = s * (1.f / NN);
}

// ---------------- kv partials: 8 N-splits of 128 rows each ----------------
__global__ __launch_bounds__(256) void kv_part(
    const float* __restrict__ k, const float* __restrict__ v, float* __restrict__ kvp)
{
    int bh = blockIdx.x, b = bh >> 3, h = bh & 7;
    int sp = blockIdx.y;
    __shared__ float sk[8][64], sv[8][64];
    int t = threadIdx.x;
    int dI = (t >> 4) << 2, eI = (t & 15) << 2;
    const float* kb = k + b * NN * CC + h * 64;
    const float* vb = v + b * NN * CC + h * 64;
    float acc[4][4] = {};
    int n0s = sp * 128, n0e = n0s + 128;
    for (int n0 = n0s; n0 < n0e; n0 += 8) {
#pragma unroll
        for (int j = 0; j < 2; j++) {
            int idx = t + j * 256;
            int rr = idx >> 6, cc = idx & 63;
            sk[rr][cc] = kb[(n0 + rr) * CC + cc];
            sv[rr][cc] = vb[(n0 + rr) * CC + cc];
        }
        __syncthreads();
#pragma unroll
        for (int r = 0; r < 8; r++) {
            float a[4], bv4[4];
#pragma unroll
            for (int i = 0; i < 4; i++) a[i] = sk[r][dI + i];
#pragma unroll
            for (int j = 0; j < 4; j++) bv4[j] = sv[r][eI + j];
#pragma unroll
            for (int i = 0; i < 4; i++)
#pragma unroll
                for (int j = 0; j < 4; j++)
                    acc[i][j] += a[i] * bv4[j];
        }
        __syncthreads();
    }
    float* dst = kvp + (sp * 32 + bh) * 4096;
#pragma unroll
    for (int i = 0; i < 4; i++)
#pragma unroll
        for (int j = 0; j < 4; j++)
            dst[(dI + i) * 64 + eI + j] = acc[i][j];
}

__global__ void kv_reduce(const float* __restrict__ kvp, float* __restrict__ kv) {
    int idx = blockIdx.x * 256 + threadIdx.x;   // 131072
    float s = 0.f;
#pragma unroll
    for (int sp = 0; sp < 8; sp++) s += kvp[sp * 131072 + idx];
    kv[idx] = s * (1.f / NN);
}

// ---------------- attention output + x_local add + fused LayerNorm ----------------
__global__ __launch_bounds__(512) void attn_ln_kernel(
    const float* __restrict__ q, const float* __restrict__ km,
    const float* __restrict__ kv, const float* __restrict__ xloc,
    const float* __restrict__ lng, const float* __restrict__ lnb,
    float* __restrict__ x, __half* __restrict__ xnh)
{
    int row = blockIdx.x;
    int b = row >> 10;
    int c = threadIdx.x;              // 512 = 16 warps
    int warp = c >> 5, lane = c & 31;
    __shared__ float qs[512];
    __shared__ float zp[16];          // per-warp q*km partial sums
    __shared__ float rs[16], rq[16];  // LN partials
    float qv = q[(size_t)row * CC + c];
    qs[c] = qv;
    float prod = qv * km[b * CC + c];
#pragma unroll
    for (int o = 16; o; o >>= 1) prod += __shfl_xor_sync(0xffffffffu, prod, o);
    if (lane == 0) zp[warp] = prod;
    __syncthreads();                  // qs full + zp ready
    int h = c >> 6, e = c & 63;
    float z = 1.f / (zp[h * 2] + zp[h * 2 + 1] + 1e-6f);
    const float* kvp = kv + ((b * 8 + h) * 64) * 64 + e;
    float acc = 0.f;
#pragma unroll 8
    for (int d = 0; d < 64; d++) acc += qs[h * 64 + d] * kvp[d * 64];
    float xv = acc * z + xloc[(size_t)row * CC + c];
    x[(size_t)row * CC + c] = xv;
    float s = xv, sq = xv * xv;
#pragma unroll
    for (int o = 16; o; o >>= 1) {
        s  += __shfl_xor_sync(0xffffffffu, s, o);
        sq += __shfl_xor_sync(0xffffffffu, sq, o);
    }
    if (lane == 0) { rs[warp] = s; rq[warp] = sq; }
    __syncthreads();
    float tot = 0.f, totq = 0.f;
#pragma unroll
    for (int j = 0; j < 16; j++) { tot += rs[j]; totq += rq[j]; }
    float mu = tot * (1.f / CC);
    float var = totq * (1.f / CC) - mu * mu;
    float inv = rsqrtf(var + 1e-5f);
    xnh[(size_t)row * CC + c] = __float2half_rn((xv - mu) * inv * lng[c] + lnb[c]);
}

// ---------------- disagreement phase 1 ----------------
__global__ void disagree_part(const float* __restrict__ x, int rowsPerBlk, int rowStride,
                              int strideB, int strideH,
                              float* __restrict__ pvec, float* __restrict__ pdiag)
{
    int bh = blockIdx.x, b = bh >> 3, h = bh & 7;
    int s = blockIdx.y, S = gridDim.y;
    const float* p = x + b * strideB + h * strideH + s * rowsPerBlk * rowStride;
    int l = threadIdx.x; // 32
    float s0 = 0.f, s1 = 0.f, diag = 0.f;
    for (int n = 0; n < rowsPerBlk; n++) {
        const float* r = p + n * rowStride;
        float v0 = r[l], v1 = r[l + 32];
        float sq = v0 * v0 + v1 * v1;
#pragma unroll
        for (int o = 16; o; o >>= 1) sq += __shfl_xor_sync(0xffffffffu, sq, o);
        float inv = 1.f / fmaxf(sqrtf(sq), 1e-12f);
        float h0 = v0 * inv, h1 = v1 * inv;
        s0 += h0; s1 += h1;
        diag += h0 * h0 + h1 * h1;
    }
    float* pv = pvec + (bh * S + s) * 64;
    pv[l] = s0; pv[l + 32] = s1;
#pragma unroll
    for (int o = 16; o; o >>= 1) diag += __shfl_xor_sync(0xffffffffu, diag, o);
    if (l == 0) pdiag[bh * S + s] = diag;
}

__global__ void disagree_reduce(const float* __restrict__ pvec, const float* __restrict__ pdiag,
                                int S, double* __restrict__ Lb)
{
    int bh = blockIdx.x;
    int l = threadIdx.x; // 64
    double v = 0.0;
    for (int s = 0; s < S; s++) v += (double)pvec[(bh * S + s) * 64 + l];
    __shared__ double sh[64];
    sh[l] = v * v;
    __syncthreads();
    for (int o = 32; o; o >>= 1) {
        if (l < o) sh[l] += sh[l + o];
        __syncthreads();
    }
    if (l == 0) {
        double d = 0.0;
        for (int s = 0; s < S; s++) d += (double)pdiag[bh * S + s];
        Lb[bh] = sh[0] - d;
    }
}

__global__ void disagree_small(const float* __restrict__ x, int nRows, int rowStride,
                               int strideB, int strideH, double* __restrict__ Lb)
{
    int bh = blockIdx.x, b = bh >> 3, h = bh & 7;
    const float* p = x + b * strideB + h * strideH;
    int l = threadIdx.x; // 32
    double s0 = 0.0, s1 = 0.0, diag = 0.0;
    for (int n = 0; n < nRows; n++) {
        const float* r = p + n * rowStride;
        float v0 = r[l], v1 = r[l + 32];
        float sq = v0 * v0 + v1 * v1;
#pragma unroll
        for (int o = 16; o; o >>= 1) sq += __shfl_xor_sync(0xffffffffu, sq, o);
        float inv = 1.f / fmaxf(sqrtf(sq), 1e-12f);
        float h0 = v0 * inv, h1 = v1 * inv;
        s0 += (double)h0; s1 += (double)h1;
        diag += (double)(h0 * h0 + h1 * h1);
    }
    double val = s0 * s0 + s1 * s1;
#pragma unroll
    for (int o = 16; o; o >>= 1) {
        val += __shfl_xor_sync(0xffffffffu, val, o);
        diag += __shfl_xor_sync(0xffffffffu, diag, o);
    }
    if (l == 0) Lb[bh] = val - diag;
}

// ---------------- final loss combine ----------------
__global__ void finish_loss(const double* __restrict__ Lb, float* dst, int doWrite) {
    if (doWrite && threadIdx.x == 0 && blockIdx.x == 0) {
        double l0 = 0.0, l1 = 0.0, l2 = 0.0;
        for (int i = 0; i < 32; i++) { l0 += Lb[i]; l1 += Lb[32 + i]; l2 += Lb[64 + i]; }
        double dbig = 4.0 * 8.0 * 1024.0 * 1024.0;
        double dsml = 4.0 * 8.0 * 64.0 * 64.0;
        dst[0] = (float)((l0 / dbig + l1 / dsml + l2 / dbig) / 3.0);
    }
}

// ---------------- launch ----------------
extern "C" void kernel_launch(void* const* d_in, const int* in_sizes, int n_in,
                              void* d_out, int out_size)
{
    const float* Q      = (const float*)d_in[0];
    const int*   adj    = (const int*)  d_in[1];
    const float* Wq     = (const float*)d_in[2];
    const float* bq     = (const float*)d_in[3];
    const float* Wk     = (const float*)d_in[4];
    const float* bk     = (const float*)d_in[5];
    const float* Wv     = (const float*)d_in[6];
    const float* bv     = (const float*)d_in[7];
    const float* scp    = (const float*)d_in[8];
    const float* Wconv  = (const float*)d_in[9];
    const float* bconv  = (const float*)d_in[10];
    const float* W2     = (const float*)d_in[11];
    const float* b2     = (const float*)d_in[12];
    const float* ln_g   = (const float*)d_in[13];
    const float* ln_b   = (const float*)d_in[14];
    const float* Wo     = (const float*)d_in[15];
    const float* bo     = (const float*)d_in[16];
    float* out = (float*)d_out;

    float *q, *k, *v, *part, *xloc, *x, *km, *kmp, *kv, *kvp, *pvec, *pdiag, *invs;
    __half *Qh, *vh, *convh, *xnh, *WT, *WqT, *WkT, *WvT, *W2T, *WoT;
    double* Lb;
    cudaGetSymbolAddress((void**)&q,     g_q);
    cudaGetSymbolAddress((void**)&k,     g_k);
    cudaGetSymbolAddress((void**)&v,     g_v);
    cudaGetSymbolAddress((void**)&Qh,    g_Qh);
    cudaGetSymbolAddress((void**)&vh,    g_vh);
    cudaGetSymbolAddress((void**)&convh, g_convh);
    cudaGetSymbolAddress((void**)&xnh,   g_xnh);
    cudaGetSymbolAddress((void**)&WT,    g_WT);
    cudaGetSymbolAddress((void**)&WqT,   g_WqT);
    cudaGetSymbolAddress((void**)&WkT,   g_WkT);
    cudaGetSymbolAddress((void**)&WvT,   g_WvT);
    cudaGetSymbolAddress((void**)&W2T,   g_W2T);
    cudaGetSymbolAddress((void**)&WoT,   g_WoT);
    cudaGetSymbolAddress((void**)&part,  g_part);
    cudaGetSymbolAddress((void**)&xloc,  g_xloc);
    cudaGetSymbolAddress((void**)&x,     g_x);
    cudaGetSymbolAddress((void**)&km,    g_km);
    cudaGetSymbolAddress((void**)&kmp,   g_kmp);
    cudaGetSymbolAddress((void**)&kv,    g_kv);
    cudaGetSymbolAddress((void**)&kvp,   g_kvp);
    cudaGetSymbolAddress((void**)&pvec,  g_pvec);
    cudaGetSymbolAddress((void**)&pdiag, g_pdiag);
    cudaGetSymbolAddress((void**)&invs,  g_invs);
    cudaGetSymbolAddress((void**)&Lb,    g_lossbh);

    // dynamic-smem opt-in (host attribute set; not a stream op, graph-capture safe)
    cudaFuncSetAttribute(gemm_qkv,     cudaFuncAttributeMaxDynamicSharedMemorySize, SMEM_BYTES);
    cudaFuncSetAttribute(gemm_plain,   cudaFuncAttributeMaxDynamicSharedMemorySize, SMEM_BYTES);
    cudaFuncSetAttribute(gemm_conv_sk, cudaFuncAttributeMaxDynamicSharedMemorySize, SMEM_BYTES);

    dim3 gG(4, 32);           // 128x128 tiles over 4096x512 => 128 CTAs
    dim3 gG3(4, 32, 3);       // qkv => 384 CTAs
    dim3 gConv(4, 32, 2);     // conv split-K=2 => 256 CTAs
    const int CVT_GRID = MR * CC / 2048;   // to_half grid (8 floats/thread)

    invs_kernel<<<2, 256>>>(scp, invs);

    // weight prep (half, [n][k] layout)
    transpose512<<<dim3(16, 16, 5), dim3(32, 8)>>>(Wq, Wk, Wv, W2, Wo, WqT, WkT, WvT, W2T, WoT);
    transpose_wconv<<<512, 512>>>(Wconv, WT);

    // A-operand prep + projections (fused q/k/v over grid.z; v also emitted as half)
    to_half<<<CVT_GRID, 256>>>(Q, Qh);
    gemm_qkv<<<gG3, 256, SMEM_BYTES>>>(Qh, WqT, WkT, WvT, bq, bk, bv, q, k, v, vh);

    // loss_local on head-view of v
    disagree_part<<<dim3(32, 32), 32>>>(v, NN / 32, CC, NN * CC, DD, pvec, pdiag);
    disagree_reduce<<<32, 64>>>(pvec, pdiag, 32, Lb + 0);

    // local branch: split-K conv GEMM (fused gather) + reduce, then W2 GEMM
    gemm_conv_sk<<<gConv, 256, SMEM_BYTES>>>(vh, WT, part, adj);
    conv_reduce<<<MR * CC / 256, 256>>>(part, bconv, convh);
    gemm_plain<<<gG, 256, SMEM_BYTES>>>(convh, W2T, b2, xloc);

    // q/k elementwise transform (one launch)
    qk_focus<<<dim3(MR, 2), 256>>>(q, k, invs);

    // kmean, kv
    kmean_part<<<dim3(8, BB), 512>>>(k, kmp);
    kmean_red<<<8, 256>>>(kmp, km);
    kv_part<<<dim3(32, 8), 256>>>(k, v, kvp);
    kv_reduce<<<512, 256>>>(kvp, kv);

    // loss_kv
    disagree_small<<<32, 32>>>(kv, DD, DD, HH * DD * DD, DD * DD, Lb + 32);

    // attention out + local add + fused LayerNorm (xn written as half)
    attn_ln_kernel<<<MR, 512>>>(q, km, kv, xloc, ln_g, ln_b, x, xnh);

    // loss_out on flat reshape view
    disagree_part<<<dim3(32, 32), 32>>>(x, NN / 32, DD, NN * CC, NN * CC / HH, pvec, pdiag);
    disagree_reduce<<<32, 64>>>(pvec, pdiag, 32, Lb + 64);

    // output projection
    gemm_plain<<<gG, 256, SMEM_BYTES>>>(xnh, WoT, bo, out);

    // loss scalar appended after the (B,N,C) output, if the buffer has room
    finish_loss<<<1, 32>>>(Lb, out + MR * CC, (out_size > MR * CC) ? 1 : 0);
}